// round 1
// baseline (speedup 1.0000x reference)
#include <cuda_runtime.h>

// PeripheralDWConv2d: depthwise 51x51 conv, weight = expand(weight_comp, IDX_MAP) + kpe
// x: [16,128,64,64] f32, weight_comp: [128,169] f32, kpe: [51,51] f32, out: [16,128,64,64] f32

#define KSZ 51
#define PP  13
#define RAD 25
#define TILE_H 114          // 64 + 2*25
#define TSTRIDE 116         // padded row stride (float4-aligned, covers max col 115)
#define WROW 52             // weight row padded to 52 (dx=51 tap is zero)
#define NCH 128
#define IMGS 2048           // 16 * 128

// Dense per-channel weights, padded: g_wpad[c][dy][dx], dx in [0,52)
__device__ float g_wpad[NCH * KSZ * WROW];

// position of quantise(a) in coords [0,1,2,4,8,16,25] for a in [0,25]
__constant__ int c_qpos[26] = {0,1,2,2,3,3,3,3,4,4,4,4,4,4,4,4,
                               5,5,5,5,5,5,5,5,5,6};

__global__ void build_weights_kernel(const float* __restrict__ wc,
                                     const float* __restrict__ kpe) {
    int t = blockIdx.x * blockDim.x + threadIdx.x;
    const int total = NCH * KSZ * WROW;
    if (t >= total) return;
    int c  = t / (KSZ * WROW);
    int r  = t - c * (KSZ * WROW);
    int dy = r / WROW;
    int dx = r - dy * WROW;
    float v = 0.f;
    if (dx < KSZ) {
        int oi = dy - RAD; int ai = oi < 0 ? -oi : oi;
        int ii = 6 + (oi < 0 ? -c_qpos[ai] : c_qpos[ai]);
        int oj = dx - RAD; int aj = oj < 0 ? -oj : oj;
        int jj = 6 + (oj < 0 ? -c_qpos[aj] : c_qpos[aj]);
        v = wc[c * (PP * PP) + ii * PP + jj] + kpe[dy * KSZ + dx];
    }
    g_wpad[t] = v;
}

__global__ __launch_bounds__(256, 3)
void dwconv_kernel(const float* __restrict__ x, float* __restrict__ out) {
    extern __shared__ float sm[];
    float* tile = sm;                        // TILE_H * TSTRIDE floats
    float* wsm  = sm + TILE_H * TSTRIDE;     // KSZ * WROW floats

    const int bc = blockIdx.x;               // b*128 + c
    const int c  = bc & (NCH - 1);
    const float* img = x + (size_t)bc * 4096;

    // Load padded input tile (zeros outside [0,64)^2)
    for (int i = threadIdx.x; i < TILE_H * TSTRIDE; i += 256) {
        int rr = i / TSTRIDE;
        int cc = i - rr * TSTRIDE;
        int gh = rr - RAD, gw = cc - RAD;
        float v = 0.f;
        if ((unsigned)gh < 64u && (unsigned)gw < 64u)
            v = img[gh * 64 + gw];
        tile[i] = v;
    }
    // Load this channel's dense weights
    for (int i = threadIdx.x; i < KSZ * WROW; i += 256)
        wsm[i] = g_wpad[c * (KSZ * WROW) + i];
    __syncthreads();

    // Thread computes a 2(h) x 8(w) output block
    const int tw = threadIdx.x & 7;          // 0..7  -> w block
    const int th = threadIdx.x >> 3;         // 0..31 -> h block
    const int w0 = tw * 8;
    const int h0 = th * 2;

    float acc0[8], acc1[8];
#pragma unroll
    for (int j = 0; j < 8; ++j) { acc0[j] = 0.f; acc1[j] = 0.f; }

    for (int dy = 0; dy < KSZ; ++dy) {
        const float* r0 = tile + (h0 + dy) * TSTRIDE + w0;
        const float* r1 = r0 + TSTRIDE;
        const float* wr = wsm + dy * WROW;

        float win0[12], win1[12];
        *(float4*)&win0[0] = *(const float4*)(r0);
        *(float4*)&win0[4] = *(const float4*)(r0 + 4);
        *(float4*)&win1[0] = *(const float4*)(r1);
        *(float4*)&win1[4] = *(const float4*)(r1 + 4);

#pragma unroll
        for (int blk = 0; blk < 13; ++blk) {
            *(float4*)&win0[8] = *(const float4*)(r0 + blk * 4 + 8);
            *(float4*)&win1[8] = *(const float4*)(r1 + blk * 4 + 8);
#pragma unroll
            for (int k = 0; k < 4; ++k) {
                float wv = wr[blk * 4 + k];
#pragma unroll
                for (int j = 0; j < 8; ++j) {
                    acc0[j] = fmaf(wv, win0[k + j], acc0[j]);
                    acc1[j] = fmaf(wv, win1[k + j], acc1[j]);
                }
            }
#pragma unroll
            for (int i = 0; i < 8; ++i) {
                win0[i] = win0[i + 4];
                win1[i] = win1[i + 4];
            }
        }
    }

    float* o = out + (size_t)bc * 4096 + h0 * 64 + w0;
    *(float4*)(o)      = *(float4*)&acc0[0];
    *(float4*)(o + 4)  = *(float4*)&acc0[4];
    *(float4*)(o + 64) = *(float4*)&acc1[0];
    *(float4*)(o + 68) = *(float4*)&acc1[4];
}

extern "C" void kernel_launch(void* const* d_in, const int* in_sizes, int n_in,
                              void* d_out, int out_size) {
    const float* x   = (const float*)d_in[0];   // 16*128*64*64
    const float* wc  = (const float*)d_in[1];   // 128*169
    const float* kpe = (const float*)d_in[2];   // 51*51
    float* out = (float*)d_out;

    const int total_w = NCH * KSZ * WROW;
    build_weights_kernel<<<(total_w + 255) / 256, 256>>>(wc, kpe);

    const size_t smem = (size_t)(TILE_H * TSTRIDE + KSZ * WROW) * sizeof(float);
    cudaFuncSetAttribute(dwconv_kernel,
                         cudaFuncAttributeMaxDynamicSharedMemorySize, (int)smem);
    dwconv_kernel<<<IMGS, 256, smem>>>(x, out);
}

// round 2
// speedup vs baseline: 1.0457x; 1.0457x over previous
#include <cuda_runtime.h>

// PeripheralDWConv2d: depthwise 51x51 conv, weight = expand(weight_comp, IDX_MAP) + kpe
// x: [16,128,64,64] f32, weight_comp: [128,169] f32, kpe: [51,51] f32, out f32.

#define KSZ 51
#define PP  13
#define RAD 25
#define NCH 128
#define WROW 52            // weight row padded to 52 floats (13 quads)
#define TQ   33            // quads per tile row (odd mod 8 -> conflict-free rows)
#define TROWS 82           // 32 output rows + 2*25 halo
#define NBLK 13            // 13 quad-blocks of dx taps (52 = 13*4, tap 51 zero)

// Dense per-channel weights, padded: g_wpad[c][dy][dx], dx in [0,52)
__device__ float g_wpad[NCH * KSZ * WROW];

// position of quantise(a) in coords [0,1,2,4,8,16,25] for a in [0,25]
__constant__ int c_qpos[26] = {0,1,2,2,3,3,3,3,4,4,4,4,4,4,4,4,
                               5,5,5,5,5,5,5,5,5,6};

__global__ void build_weights_kernel(const float* __restrict__ wc,
                                     const float* __restrict__ kpe) {
    int t = blockIdx.x * blockDim.x + threadIdx.x;
    const int total = NCH * KSZ * WROW;
    if (t >= total) return;
    int c  = t / (KSZ * WROW);
    int r  = t - c * (KSZ * WROW);
    int dy = r / WROW;
    int dx = r - dy * WROW;
    float v = 0.f;
    if (dx < KSZ) {
        int oi = dy - RAD; int ai = oi < 0 ? -oi : oi;
        int ii = 6 + (oi < 0 ? -c_qpos[ai] : c_qpos[ai]);
        int oj = dx - RAD; int aj = oj < 0 ? -oj : oj;
        int jj = 6 + (oj < 0 ? -c_qpos[aj] : c_qpos[aj]);
        v = wc[c * (PP * PP) + ii * PP + jj] + kpe[dy * KSZ + dx];
    }
    g_wpad[t] = v;
}

// quad-level XOR swizzle: bijective on [0,32), makes chunk bases distinct mod 8
__device__ __forceinline__ int swz(int q) { return q ^ ((q >> 1) & 6); }

__global__ __launch_bounds__(128, 4)
void dwconv_kernel(const float* __restrict__ x, float* __restrict__ out) {
    extern __shared__ float sm[];
    float* tile = sm;                      // TROWS * TQ quads (floats: *4)
    float* wsm  = sm + TROWS * TQ * 4;     // KSZ * WROW floats

    const int blk  = blockIdx.x;           // 2 CTAs per (b,c) image
    const int img  = blk >> 1;
    const int half = blk & 1;
    const int c    = img & (NCH - 1);
    const float* src = x + (size_t)img * 4096;
    const int tid = threadIdx.x;

    // ---- fill padded tile (quads, swizzled) ----
    const int y_base = half * 32;
    for (int i = tid; i < TROWS * 32; i += 128) {
        int r = i >> 5;                    // tile row 0..81
        int q = i & 31;                    // logical quad 0..31
        int gh = r + y_base - RAD;
        float4 v = make_float4(0.f, 0.f, 0.f, 0.f);
        if ((unsigned)gh < 64u) {
            const float* row = src + gh * 64;
            int gw = q * 4 - RAD;
            float* vp = (float*)&v;
#pragma unroll
            for (int j = 0; j < 4; ++j) {
                int w = gw + j;
                if ((unsigned)w < 64u) vp[j] = row[w];
            }
        }
        *(float4*)&tile[(r * TQ + swz(q)) * 4] = v;
    }
    // ---- channel weights to smem ----
    for (int i = tid; i < KSZ * WROW; i += 128)
        wsm[i] = g_wpad[c * (KSZ * WROW) + i];
    __syncthreads();

    // thread: 1 output row x 16 outputs
    const int tx = tid & 3;                 // x chunk: x0 = 16*tx
    const int ty = tid >> 2;                // 0..31
    const int qx = tx * 4;                  // logical quad base

    // precomputed swizzled float offsets within a row for the 17 window quads
    int offs[17];
#pragma unroll
    for (int n = 0; n < 17; ++n) offs[n] = swz(qx + n) * 4;

    float acc[16];
#pragma unroll
    for (int j = 0; j < 16; ++j) acc[j] = 0.f;

    const float* trow = tile + ty * (TQ * 4);
    const float* wr   = wsm;

    for (int dy = 0; dy < KSZ; ++dy) {
        alignas(16) float win[20];          // 5 rolling quads
#pragma unroll
        for (int n = 0; n < 4; ++n)
            *(float4*)&win[n * 4] = *(const float4*)&trow[offs[n]];

#pragma unroll
        for (int b = 0; b < NBLK; ++b) {
            // fetch quad b+4 into slot (b+4)%5 (used late in this block)
            *(float4*)&win[((b + 4) % 5) * 4] = *(const float4*)&trow[offs[b + 4]];
            float4 wq = *(const float4*)&wr[b * 4];   // 4 taps, uniform broadcast
            const float* wk = (const float*)&wq;
#pragma unroll
            for (int k = 0; k < 4; ++k) {
                float wv = wk[k];
#pragma unroll
                for (int j = 0; j < 16; ++j) {
                    int f = k + j;                     // 0..18
                    int slot = ((b + (f >> 2)) % 5) * 4 + (f & 3);
                    acc[j] = fmaf(wv, win[slot], acc[j]);
                }
            }
        }
        trow += TQ * 4;
        wr   += WROW;
    }

    float* o = out + (size_t)img * 4096 + (y_base + ty) * 64 + tx * 16;
#pragma unroll
    for (int ch = 0; ch < 4; ++ch)
        *(float4*)&o[ch * 4] = make_float4(acc[ch*4], acc[ch*4+1],
                                           acc[ch*4+2], acc[ch*4+3]);
}

extern "C" void kernel_launch(void* const* d_in, const int* in_sizes, int n_in,
                              void* d_out, int out_size) {
    const float* x   = (const float*)d_in[0];   // 16*128*64*64
    const float* wc  = (const float*)d_in[1];   // 128*169
    const float* kpe = (const float*)d_in[2];   // 51*51
    float* out = (float*)d_out;

    const int total_w = NCH * KSZ * WROW;
    build_weights_kernel<<<(total_w + 255) / 256, 256>>>(wc, kpe);

    const size_t smem = (size_t)(TROWS * TQ * 4 + KSZ * WROW) * sizeof(float);
    cudaFuncSetAttribute(dwconv_kernel,
                         cudaFuncAttributeMaxDynamicSharedMemorySize, (int)smem);
    dwconv_kernel<<<4096, 128, smem>>>(x, out);
}

// round 3
// speedup vs baseline: 1.0460x; 1.0003x over previous
#include <cuda_runtime.h>

// PeripheralDWConv2d: depthwise 51x51 conv, weight = expand(weight_comp, IDX_MAP) + kpe
// x: [16,128,64,64] f32, weight_comp: [128,169] f32, kpe: [51,51] f32, out f32.

#define KSZ 51
#define PP  13
#define RAD 25
#define NCH 128
#define WROW 52            // weight row padded to 52 floats (13 quads)
#define TQ   33            // quads per tile row (odd mod 8 -> conflict-free rows)
#define TROWS 82           // 32 output rows + 2*25 halo
#define NBLK 13            // 13 quad-blocks of dx taps (52 = 13*4, tap 51 zero)

// Dense per-channel weights, padded: g_wpad[c][dy][dx], dx in [0,52)
__device__ float g_wpad[NCH * KSZ * WROW];

// position of quantise(a) in coords [0,1,2,4,8,16,25] for a in [0,25]
__constant__ int c_qpos[26] = {0,1,2,2,3,3,3,3,4,4,4,4,4,4,4,4,
                               5,5,5,5,5,5,5,5,5,6};

__global__ void build_weights_kernel(const float* __restrict__ wc,
                                     const float* __restrict__ kpe) {
    int t = blockIdx.x * blockDim.x + threadIdx.x;
    const int total = NCH * KSZ * WROW;
    if (t >= total) return;
    int c  = t / (KSZ * WROW);
    int r  = t - c * (KSZ * WROW);
    int dy = r / WROW;
    int dx = r - dy * WROW;
    float v = 0.f;
    if (dx < KSZ) {
        int oi = dy - RAD; int ai = oi < 0 ? -oi : oi;
        int ii = 6 + (oi < 0 ? -c_qpos[ai] : c_qpos[ai]);
        int oj = dx - RAD; int aj = oj < 0 ? -oj : oj;
        int jj = 6 + (oj < 0 ? -c_qpos[aj] : c_qpos[aj]);
        v = wc[c * (PP * PP) + ii * PP + jj] + kpe[dy * KSZ + dx];
    }
    g_wpad[t] = v;
}

// quad-level XOR swizzle: bijective on [0,32), makes chunk bases distinct mod 8
__device__ __forceinline__ int swz(int q) { return q ^ ((q >> 1) & 6); }

__global__ __launch_bounds__(128, 4)
void dwconv_kernel(const float* __restrict__ x, float* __restrict__ out) {
    extern __shared__ float sm[];
    float* tile = sm;                      // TROWS * TQ quads (floats: *4)
    float* wsm  = sm + TROWS * TQ * 4;     // KSZ * WROW floats

    const int blk  = blockIdx.x;           // 2 CTAs per (b,c) image
    const int img  = blk >> 1;
    const int half = blk & 1;
    const int c    = img & (NCH - 1);
    const float* src = x + (size_t)img * 4096;
    const int tid = threadIdx.x;

    // ---- fill padded tile (quads, swizzled) ----
    const int y_base = half * 32;
    for (int i = tid; i < TROWS * 32; i += 128) {
        int r = i >> 5;                    // tile row 0..81
        int q = i & 31;                    // logical quad 0..31
        int gh = r + y_base - RAD;
        float4 v = make_float4(0.f, 0.f, 0.f, 0.f);
        if ((unsigned)gh < 64u) {
            const float* row = src + gh * 64;
            int gw = q * 4 - RAD;
            float* vp = (float*)&v;
#pragma unroll
            for (int j = 0; j < 4; ++j) {
                int w = gw + j;
                if ((unsigned)w < 64u) vp[j] = row[w];
            }
        }
        *(float4*)&tile[(r * TQ + swz(q)) * 4] = v;
    }
    // ---- channel weights to smem ----
    for (int i = tid; i < KSZ * WROW; i += 128)
        wsm[i] = g_wpad[c * (KSZ * WROW) + i];
    __syncthreads();

    // thread: 1 output row x 16 outputs
    const int tx = tid & 3;                 // x chunk: x0 = 16*tx
    const int ty = tid >> 2;                // 0..31
    const int qx = tx * 4;                  // logical quad base

    // precomputed swizzled float offsets within a row for the 17 window quads
    int offs[17];
#pragma unroll
    for (int n = 0; n < 17; ++n) offs[n] = swz(qx + n) * 4;

    float acc[16];
#pragma unroll
    for (int j = 0; j < 16; ++j) acc[j] = 0.f;

    const float* trow = tile + ty * (TQ * 4);
    const float* wr   = wsm;

    for (int dy = 0; dy < KSZ; ++dy) {
        alignas(16) float win[20];          // 5 rolling quads
#pragma unroll
        for (int n = 0; n < 4; ++n)
            *(float4*)&win[n * 4] = *(const float4*)&trow[offs[n]];

#pragma unroll
        for (int b = 0; b < NBLK; ++b) {
            // fetch quad b+4 into slot (b+4)%5 (used late in this block)
            *(float4*)&win[((b + 4) % 5) * 4] = *(const float4*)&trow[offs[b + 4]];
            float4 wq = *(const float4*)&wr[b * 4];   // 4 taps, uniform broadcast
            const float* wk = (const float*)&wq;
#pragma unroll
            for (int k = 0; k < 4; ++k) {
                float wv = wk[k];
#pragma unroll
                for (int j = 0; j < 16; ++j) {
                    int f = k + j;                     // 0..18
                    int slot = ((b + (f >> 2)) % 5) * 4 + (f & 3);
                    acc[j] = fmaf(wv, win[slot], acc[j]);
                }
            }
        }
        trow += TQ * 4;
        wr   += WROW;
    }

    float* o = out + (size_t)img * 4096 + (y_base + ty) * 64 + tx * 16;
#pragma unroll
    for (int ch = 0; ch < 4; ++ch)
        *(float4*)&o[ch * 4] = make_float4(acc[ch*4], acc[ch*4+1],
                                           acc[ch*4+2], acc[ch*4+3]);
}

extern "C" void kernel_launch(void* const* d_in, const int* in_sizes, int n_in,
                              void* d_out, int out_size) {
    const float* x   = (const float*)d_in[0];   // 16*128*64*64
    const float* wc  = (const float*)d_in[1];   // 128*169
    const float* kpe = (const float*)d_in[2];   // 51*51
    float* out = (float*)d_out;

    const int total_w = NCH * KSZ * WROW;
    build_weights_kernel<<<(total_w + 255) / 256, 256>>>(wc, kpe);

    const size_t smem = (size_t)(TROWS * TQ * 4 + KSZ * WROW) * sizeof(float);
    cudaFuncSetAttribute(dwconv_kernel,
                         cudaFuncAttributeMaxDynamicSharedMemorySize, (int)smem);
    dwconv_kernel<<<4096, 128, smem>>>(x, out);
}

// round 4
// speedup vs baseline: 1.0485x; 1.0024x over previous
#include <cuda_runtime.h>

// PeripheralDWConv2d: depthwise 51x51 conv, weight = expand(weight_comp, IDX_MAP) + kpe
// x: [16,128,64,64] f32, weight_comp: [128,169] f32, kpe: [51,51] f32, out f32.

#define KSZ 51
#define PP  13
#define RAD 25
#define NCH 128
#define WROW 52            // weight row padded to 52 floats (13 quads)
#define TQ   33            // quads per tile row (odd mod 8 -> conflict-free rows)
#define TROWS 82           // 32 output rows + 2*25 halo
#define NBLK 13            // 13 quad-blocks of dx taps (52 = 13*4, tap 51 zero)

// Dense per-channel weights, padded: g_wpad[c][dy][dx], dx in [0,52)
__device__ float g_wpad[NCH * KSZ * WROW];

// position of quantise(a) in coords [0,1,2,4,8,16,25] for a in [0,25]
__constant__ int c_qpos[26] = {0,1,2,2,3,3,3,3,4,4,4,4,4,4,4,4,
                               5,5,5,5,5,5,5,5,5,6};

__global__ void build_weights_kernel(const float* __restrict__ wc,
                                     const float* __restrict__ kpe) {
    int t = blockIdx.x * blockDim.x + threadIdx.x;
    const int total = NCH * KSZ * WROW;
    if (t >= total) return;
    int c  = t / (KSZ * WROW);
    int r  = t - c * (KSZ * WROW);
    int dy = r / WROW;
    int dx = r - dy * WROW;
    float v = 0.f;
    if (dx < KSZ) {
        int oi = dy - RAD; int ai = oi < 0 ? -oi : oi;
        int ii = 6 + (oi < 0 ? -c_qpos[ai] : c_qpos[ai]);
        int oj = dx - RAD; int aj = oj < 0 ? -oj : oj;
        int jj = 6 + (oj < 0 ? -c_qpos[aj] : c_qpos[aj]);
        v = wc[c * (PP * PP) + ii * PP + jj] + kpe[dy * KSZ + dx];
    }
    g_wpad[t] = v;
}

// quad-level XOR swizzle: bijective on [0,32), makes chunk bases distinct mod 8
__device__ __forceinline__ int swz(int q) { return q ^ ((q >> 1) & 6); }

__global__ __launch_bounds__(128, 4)
void dwconv_kernel(const float* __restrict__ x, float* __restrict__ out) {
    extern __shared__ float sm[];
    float* tile = sm;                      // TROWS * TQ quads (floats: *4)
    float* wsm  = sm + TROWS * TQ * 4;     // KSZ * WROW floats

    const int blk  = blockIdx.x;           // 2 CTAs per (b,c) image
    const int img  = blk >> 1;
    const int half = blk & 1;
    const int c    = img & (NCH - 1);
    const float* src = x + (size_t)img * 4096;
    const int tid = threadIdx.x;

    // ---- fill padded tile (quads, swizzled) ----
    const int y_base = half * 32;
    for (int i = tid; i < TROWS * 32; i += 128) {
        int r = i >> 5;                    // tile row 0..81
        int q = i & 31;                    // logical quad 0..31
        int gh = r + y_base - RAD;
        float4 v = make_float4(0.f, 0.f, 0.f, 0.f);
        if ((unsigned)gh < 64u) {
            const float* row = src + gh * 64;
            int gw = q * 4 - RAD;
            float* vp = (float*)&v;
#pragma unroll
            for (int j = 0; j < 4; ++j) {
                int w = gw + j;
                if ((unsigned)w < 64u) vp[j] = row[w];
            }
        }
        *(float4*)&tile[(r * TQ + swz(q)) * 4] = v;
    }
    // ---- channel weights to smem ----
    for (int i = tid; i < KSZ * WROW; i += 128)
        wsm[i] = g_wpad[c * (KSZ * WROW) + i];
    __syncthreads();

    // thread: 1 output row x 16 outputs
    const int tx = tid & 3;                 // x chunk: x0 = 16*tx
    const int ty = tid >> 2;                // 0..31
    const int qx = tx * 4;                  // logical quad base

    // precomputed swizzled float offsets within a row for the 17 window quads
    int offs[17];
#pragma unroll
    for (int n = 0; n < 17; ++n) offs[n] = swz(qx + n) * 4;

    float acc[16];
#pragma unroll
    for (int j = 0; j < 16; ++j) acc[j] = 0.f;

    const float* trow = tile + ty * (TQ * 4);
    const float* wr   = wsm;

    for (int dy = 0; dy < KSZ; ++dy) {
        alignas(16) float win[20];          // 5 rolling quads
#pragma unroll
        for (int n = 0; n < 4; ++n)
            *(float4*)&win[n * 4] = *(const float4*)&trow[offs[n]];

#pragma unroll
        for (int b = 0; b < NBLK; ++b) {
            // fetch quad b+4 into slot (b+4)%5 (used late in this block)
            *(float4*)&win[((b + 4) % 5) * 4] = *(const float4*)&trow[offs[b + 4]];
            float4 wq = *(const float4*)&wr[b * 4];   // 4 taps, uniform broadcast
            const float* wk = (const float*)&wq;
#pragma unroll
            for (int k = 0; k < 4; ++k) {
                float wv = wk[k];
#pragma unroll
                for (int j = 0; j < 16; ++j) {
                    int f = k + j;                     // 0..18
                    int slot = ((b + (f >> 2)) % 5) * 4 + (f & 3);
                    acc[j] = fmaf(wv, win[slot], acc[j]);
                }
            }
        }
        trow += TQ * 4;
        wr   += WROW;
    }

    float* o = out + (size_t)img * 4096 + (y_base + ty) * 64 + tx * 16;
#pragma unroll
    for (int ch = 0; ch < 4; ++ch)
        *(float4*)&o[ch * 4] = make_float4(acc[ch*4], acc[ch*4+1],
                                           acc[ch*4+2], acc[ch*4+3]);
}

extern "C" void kernel_launch(void* const* d_in, const int* in_sizes, int n_in,
                              void* d_out, int out_size) {
    const float* x   = (const float*)d_in[0];   // 16*128*64*64
    const float* wc  = (const float*)d_in[1];   // 128*169
    const float* kpe = (const float*)d_in[2];   // 51*51
    float* out = (float*)d_out;

    const int total_w = NCH * KSZ * WROW;
    build_weights_kernel<<<(total_w + 255) / 256, 256>>>(wc, kpe);

    const size_t smem = (size_t)(TROWS * TQ * 4 + KSZ * WROW) * sizeof(float);
    cudaFuncSetAttribute(dwconv_kernel,
                         cudaFuncAttributeMaxDynamicSharedMemorySize, (int)smem);
    dwconv_kernel<<<4096, 128, smem>>>(x, out);
}

// round 5
// speedup vs baseline: 2.4915x; 2.3762x over previous
#include <cuda_runtime.h>

// PeripheralDWConv2d via hybrid FFT: FFT along x (128-pt), direct 51-tap conv
// along y in the frequency domain, inverse FFT, crop.
// x: [16,128,64,64] f32, weight_comp: [128,169] f32, kpe: [51,51] f32, out f32.

#define KSZ 51
#define PP  13
#define RAD 25
#define NCH 128
#define WROW 52
#define NIMG 2048          // 16*128
#define NROWS 131072       // NIMG*64
#define NB 65              // stored hermitian bins of 128-pt FFT
#define YDIM 64
#define XPAD 114           // 64 + 2*25 padded y rows in yconv smem

__device__ float  g_wpad[NCH * KSZ * WROW];          // dense weights (wc expand + kpe)
__device__ float2 g_tw[64];                          // twiddles exp(-i*pi*q/64)
__device__ float2 g_wf[NCH * KSZ * NB];              // conj spectra of weight rows
__device__ float2 g_xf[(size_t)NROWS * NB];          // input row spectra
__device__ float2 g_sf[(size_t)NROWS * NB];          // output row spectra

// position of quantise(a) in coords [0,1,2,4,8,16,25] for a in [0,25]
__constant__ int c_qpos[26] = {0,1,2,2,3,3,3,3,4,4,4,4,4,4,4,4,
                               5,5,5,5,5,5,5,5,5,6};

__global__ void build_weights_kernel(const float* __restrict__ wc,
                                     const float* __restrict__ kpe) {
    int t = blockIdx.x * blockDim.x + threadIdx.x;
    const int total = NCH * KSZ * WROW;
    if (t >= total) return;
    int c  = t / (KSZ * WROW);
    int r  = t - c * (KSZ * WROW);
    int dy = r / WROW;
    int dx = r - dy * WROW;
    float v = 0.f;
    if (dx < KSZ) {
        int oi = dy - RAD; int ai = oi < 0 ? -oi : oi;
        int ii = 6 + (oi < 0 ? -c_qpos[ai] : c_qpos[ai]);
        int oj = dx - RAD; int aj = oj < 0 ? -oj : oj;
        int jj = 6 + (oj < 0 ? -c_qpos[aj] : c_qpos[aj]);
        v = wc[c * (PP * PP) + ii * PP + jj] + kpe[dy * KSZ + dx];
    }
    g_wpad[t] = v;
}

__global__ void init_tw_kernel() {
    int q = threadIdx.x;
    if (q < 64) {
        float s, c;
        sincospif(-(float)q / 64.0f, &s, &c);
        g_tw[q] = make_float2(c, s);
    }
}

// 128-pt complex Stockham radix-2 FFT, warp-cooperative, smem ping-pong.
// buf: 256 float2 (in: buf[0..127]; out ends in buf[128..255]).
__device__ __forceinline__ void fft128(float2* buf, const float2* stw, int lane) {
    float2* cur = buf;
    float2* nxt = buf + 128;
    int m = 1;
#pragma unroll
    for (int s = 0; s < 7; ++s) {
        __syncwarp();
#pragma unroll
        for (int h = 0; h < 2; ++h) {
            int t = lane + h * 32;          // 0..63
            int q = t & ~(m - 1);
            float2 a = cur[t];
            float2 b = cur[t + 64];
            float2 w = stw[q];
            float dr = a.x - b.x, di = a.y - b.y;
            nxt[t + q]     = make_float2(a.x + b.x, a.y + b.y);
            nxt[t + q + m] = make_float2(dr * w.x - di * w.y,
                                         dr * w.y + di * w.x);
        }
        float2* tp = cur; cur = nxt; nxt = tp;
        m <<= 1;
    }
    __syncwarp();   // result in buf[128..255] (7 swaps, odd)
}

// Forward FFT of weight rows; store conjugated spectra (correlation kernel).
__global__ __launch_bounds__(256) void fft_w_kernel() {
    __shared__ float2 pp[8][256];
    __shared__ float2 stw[64];
    int tid = threadIdx.x;
    if (tid < 64) stw[tid] = g_tw[tid];
    __syncthreads();
    int lane = tid & 31, w = tid >> 5;
    int row = blockIdx.x * 8 + w;                  // c*51 + dy, < 6528
    const float* src = g_wpad + row * WROW;        // (c*51+dy)*52
    float2* buf = pp[w];
    int t0 = lane, t1 = lane + 32;
    buf[t0]      = make_float2(t0 < KSZ ? src[t0] : 0.f, 0.f);
    buf[t1]      = make_float2(t1 < KSZ ? src[t1] : 0.f, 0.f);
    buf[lane+64] = make_float2(0.f, 0.f);
    buf[lane+96] = make_float2(0.f, 0.f);
    fft128(buf, stw, lane);
    float2* res = buf + 128;
    float2* dst = g_wf + (size_t)row * NB;
    float2 r0 = res[lane];      dst[lane]      = make_float2(r0.x, -r0.y);
    float2 r1 = res[lane + 32]; dst[lane + 32] = make_float2(r1.x, -r1.y);
    if (lane == 0) { float2 r2 = res[64]; dst[64] = make_float2(r2.x, -r2.y); }
}

// Forward FFT of all input rows.
__global__ __launch_bounds__(256) void fft_x_kernel(const float* __restrict__ x) {
    __shared__ float2 pp[8][256];
    __shared__ float2 stw[64];
    int tid = threadIdx.x;
    if (tid < 64) stw[tid] = g_tw[tid];
    __syncthreads();
    int lane = tid & 31, w = tid >> 5;
    int row = blockIdx.x * 8 + w;                  // < 131072
    const float* src = x + (size_t)row * 64;
    float2* buf = pp[w];
    buf[lane]      = make_float2(src[lane], 0.f);
    buf[lane + 32] = make_float2(src[lane + 32], 0.f);
    buf[lane + 64] = make_float2(0.f, 0.f);
    buf[lane + 96] = make_float2(0.f, 0.f);
    fft128(buf, stw, lane);
    float2* res = buf + 128;
    float2* dst = g_xf + (size_t)row * NB;
    dst[lane]      = res[lane];
    dst[lane + 32] = res[lane + 32];
    if (lane == 0) dst[64] = res[64];
}

// Frequency-domain 51-tap conv along y. One CTA per (b,c) image.
__global__ __launch_bounds__(256, 2) void yconv_kernel() {
    extern __shared__ float2 sm2[];
    float2* Xs = sm2;                    // XPAD * NB
    float2* Ws = sm2 + XPAD * NB;        // KSZ * NB
    const int img = blockIdx.x;
    const int c   = img & (NCH - 1);
    const int tid = threadIdx.x;

    for (int i = tid; i < KSZ * NB; i += 256)
        Ws[i] = g_wf[c * (KSZ * NB) + i];

    const float2* xsrc = g_xf + (size_t)img * (YDIM * NB);
    for (int i = tid; i < XPAD * NB; i += 256) {
        int s = i / NB;
        int f = i - s * NB;
        float2 v = make_float2(0.f, 0.f);
        int ys = s - RAD;
        if ((unsigned)ys < (unsigned)YDIM) v = xsrc[ys * NB + f];
        Xs[i] = v;
    }
    __syncthreads();

    float2* dst = g_sf + (size_t)img * (YDIM * NB);
    for (int task = tid; task < 8 * NB; task += 256) {
        int yb = task / NB;
        int f  = task - yb * NB;
        int y0 = yb * 8;
        const float2* base = Xs + y0 * NB + f;
        const float2* wp   = Ws + f;

        float2 acc[8], win[8];
#pragma unroll
        for (int i = 0; i < 8; ++i) acc[i] = make_float2(0.f, 0.f);
#pragma unroll
        for (int j = 0; j < 7; ++j) win[j] = base[j * NB];

#pragma unroll
        for (int dy = 0; dy < KSZ; ++dy) {
            win[(dy + 7) & 7] = base[(dy + 7) * NB];
            float2 wv = wp[dy * NB];
#pragma unroll
            for (int i = 0; i < 8; ++i) {
                float2 xv = win[(dy + i) & 7];
                acc[i].x = fmaf(xv.x, wv.x, fmaf(-xv.y, wv.y, acc[i].x));
                acc[i].y = fmaf(xv.x, wv.y, fmaf( xv.y, wv.x, acc[i].y));
            }
        }
#pragma unroll
        for (int i = 0; i < 8; ++i)
            dst[(y0 + i) * NB + f] = acc[i];
    }
}

// Hermitian-expand + inverse FFT (via conj trick) + crop + write output.
__global__ __launch_bounds__(256) void ifft_kernel(float* __restrict__ out) {
    __shared__ float2 pp[8][256];
    __shared__ float2 stw[64];
    int tid = threadIdx.x;
    if (tid < 64) stw[tid] = g_tw[tid];
    __syncthreads();
    int lane = tid & 31, w = tid >> 5;
    int row = blockIdx.x * 8 + w;                  // img*64 + y
    const float2* S = g_sf + (size_t)row * NB;
    float2* buf = pp[w];

    // buf = conj(S_full): conj(S[f]) for f<=64, S[128-f] for f>64
    float2 s0 = S[lane];      buf[lane]      = make_float2(s0.x, -s0.y);
    float2 s1 = S[lane + 32]; buf[lane + 32] = make_float2(s1.x, -s1.y);
    if (lane == 0) {
        float2 v = S[64];     buf[64]        = make_float2(v.x, -v.y);
    } else {
        buf[lane + 64] = S[64 - lane];    // t=65..95 -> 128-t = 63..33
    }
    buf[lane + 96] = S[32 - lane];        // t=96..127 -> 128-t = 32..1

    fft128(buf, stw, lane);
    float2* res = buf + 128;

    float* o = out + (size_t)row * 64;
    int x0 = lane;
    int x1 = lane + 32;
    int n0 = (x0 >= RAD) ? (x0 - RAD) : (x0 + 128 - RAD);
    int n1 = x1 - RAD;
    o[x0] = res[n0].x * (1.0f / 128.0f);
    o[x1] = res[n1].x * (1.0f / 128.0f);
}

extern "C" void kernel_launch(void* const* d_in, const int* in_sizes, int n_in,
                              void* d_out, int out_size) {
    const float* x   = (const float*)d_in[0];   // 16*128*64*64
    const float* wc  = (const float*)d_in[1];   // 128*169
    const float* kpe = (const float*)d_in[2];   // 51*51
    float* out = (float*)d_out;

    init_tw_kernel<<<1, 64>>>();

    const int total_w = NCH * KSZ * WROW;
    build_weights_kernel<<<(total_w + 255) / 256, 256>>>(wc, kpe);

    fft_w_kernel<<<(NCH * KSZ) / 8, 256>>>();        // 6528 rows
    fft_x_kernel<<<NROWS / 8, 256>>>(x);             // 131072 rows

    const size_t ysmem = (size_t)(XPAD + KSZ) * NB * sizeof(float2);  // 85800 B
    cudaFuncSetAttribute(yconv_kernel,
                         cudaFuncAttributeMaxDynamicSharedMemorySize, (int)ysmem);
    yconv_kernel<<<NIMG, 256, ysmem>>>();

    ifft_kernel<<<NROWS / 8, 256>>>(out);
}

// round 6
// speedup vs baseline: 4.6442x; 1.8640x over previous
#include <cuda_runtime.h>

// PeripheralDWConv2d via hybrid FFT:
//  - pack batch pairs into complex rows (z = x[2k] + i*x[2k+1])
//  - 128-pt register/shuffle DIF FFT along x (bit-reversed slot order)
//  - direct 51-tap conv along y per frequency slot
//  - register/shuffle DIT inverse FFT (natural order out), crop, unpack.

#define KSZ 51
#define PP  13
#define RAD 25
#define NCH 128
#define WROW 52
#define NBIN 128
#define NPIMG 1024          // 8 batch-pairs * 128 channels
#define NPROWS 65536        // NPIMG * 64 y-rows
#define YDIM 64
#define XPAD 114

__device__ float  g_wpad[NCH * KSZ * WROW];
__device__ float2 g_wf[NCH * KSZ * NBIN];           // conj spectra, bitrev slots
__device__ float2 g_xf[(size_t)NPROWS * NBIN];      // packed row spectra
__device__ float2 g_sf[(size_t)NPROWS * NBIN];      // conv'd spectra

__constant__ int c_qpos[26] = {0,1,2,2,3,3,3,3,4,4,4,4,4,4,4,4,
                               5,5,5,5,5,5,5,5,5,6};

__global__ void build_weights_kernel(const float* __restrict__ wc,
                                     const float* __restrict__ kpe) {
    int t = blockIdx.x * blockDim.x + threadIdx.x;
    const int total = NCH * KSZ * WROW;
    if (t >= total) return;
    int c  = t / (KSZ * WROW);
    int r  = t - c * (KSZ * WROW);
    int dy = r / WROW;
    int dx = r - dy * WROW;
    float v = 0.f;
    if (dx < KSZ) {
        int oi = dy - RAD; int ai = oi < 0 ? -oi : oi;
        int ii = 6 + (oi < 0 ? -c_qpos[ai] : c_qpos[ai]);
        int oj = dx - RAD; int aj = oj < 0 ? -oj : oj;
        int jj = 6 + (oj < 0 ? -c_qpos[aj] : c_qpos[aj]);
        v = wc[c * (PP * PP) + ii * PP + jj] + kpe[dy * KSZ + dx];
    }
    g_wpad[t] = v;
}

__device__ __forceinline__ float2 cmulf(float2 a, float2 b) {
    return make_float2(a.x * b.x - a.y * b.y, a.x * b.y + a.y * b.x);
}
__device__ __forceinline__ float2 twid(float ang) {   // exp(i*ang)
    float s, c;
    __sincosf(ang, &s, &c);
    return make_float2(c, s);
}

#define PI2F 6.28318530717958647692f

// Forward 128-pt DIF FFT. Thread t holds elements t, t+32, t+64, t+96.
// Output: storage slot p holds spectrum bin bitrev7(p).
__device__ __forceinline__ void fft128_fwd(float2 z[4], int t) {
    {   // d = 64 (local): pairs (z0,z2),(z1,z3), W_128^{t}, W_128^{t+32}
        float2 w0 = twid(-PI2F * (float)t / 128.0f);
        float2 w1 = twid(-PI2F * (float)(t + 32) / 128.0f);
        float2 a, b;
        a = z[0]; b = z[2];
        z[0] = make_float2(a.x + b.x, a.y + b.y);
        z[2] = cmulf(make_float2(a.x - b.x, a.y - b.y), w0);
        a = z[1]; b = z[3];
        z[1] = make_float2(a.x + b.x, a.y + b.y);
        z[3] = cmulf(make_float2(a.x - b.x, a.y - b.y), w1);
    }
    {   // d = 32 (local): pairs (z0,z1),(z2,z3), W_64^{t}
        float2 w = twid(-PI2F * (float)t / 64.0f);
        float2 a, b;
        a = z[0]; b = z[1];
        z[0] = make_float2(a.x + b.x, a.y + b.y);
        z[1] = cmulf(make_float2(a.x - b.x, a.y - b.y), w);
        a = z[2]; b = z[3];
        z[2] = make_float2(a.x + b.x, a.y + b.y);
        z[3] = cmulf(make_float2(a.x - b.x, a.y - b.y), w);
    }
#pragma unroll
    for (int d = 16; d >= 1; d >>= 1) {   // shuffle stages
        float2 w = twid(-PI2F * (float)(t & (d - 1)) / (2.0f * (float)d));
        bool hi = (t & d) != 0;
#pragma unroll
        for (int j = 0; j < 4; ++j) {
            float ox = __shfl_xor_sync(0xffffffffu, z[j].x, d);
            float oy = __shfl_xor_sync(0xffffffffu, z[j].y, d);
            if (hi) z[j] = cmulf(make_float2(ox - z[j].x, oy - z[j].y), w);
            else    z[j] = make_float2(z[j].x + ox, z[j].y + oy);
        }
    }
}

// Inverse 128-pt DIT (unnormalized IDFT). Input: slot p = bin bitrev7(p).
// Output: natural order, thread t holds samples t, t+32, t+64, t+96.
__device__ __forceinline__ void fft128_inv(float2 z[4], int t) {
#pragma unroll
    for (int d = 1; d <= 16; d <<= 1) {   // shuffle stages
        float2 w = twid(PI2F * (float)(t & (d - 1)) / (2.0f * (float)d));
        bool hi = (t & d) != 0;
#pragma unroll
        for (int j = 0; j < 4; ++j) {
            float ox = __shfl_xor_sync(0xffffffffu, z[j].x, d);
            float oy = __shfl_xor_sync(0xffffffffu, z[j].y, d);
            if (hi) {   // holds v: result = u - v*w = o - z*w
                float2 vm = cmulf(z[j], w);
                z[j] = make_float2(ox - vm.x, oy - vm.y);
            } else {    // holds u: result = u + v*w = z + o*w
                float2 vo = cmulf(make_float2(ox, oy), w);
                z[j] = make_float2(z[j].x + vo.x, z[j].y + vo.y);
            }
        }
    }
    {   // len=64 (local): pairs (z0,z1),(z2,z3), W_64^{+t}
        float2 w = twid(PI2F * (float)t / 64.0f);
        float2 u, v;
        v = cmulf(z[1], w); u = z[0];
        z[0] = make_float2(u.x + v.x, u.y + v.y);
        z[1] = make_float2(u.x - v.x, u.y - v.y);
        v = cmulf(z[3], w); u = z[2];
        z[2] = make_float2(u.x + v.x, u.y + v.y);
        z[3] = make_float2(u.x - v.x, u.y - v.y);
    }
    {   // len=128 (local): pairs (z0,z2) W_128^{+t}, (z1,z3) W_128^{+(t+32)}
        float2 w0 = twid(PI2F * (float)t / 128.0f);
        float2 w1 = twid(PI2F * (float)(t + 32) / 128.0f);
        float2 u, v;
        v = cmulf(z[2], w0); u = z[0];
        z[0] = make_float2(u.x + v.x, u.y + v.y);
        z[2] = make_float2(u.x - v.x, u.y - v.y);
        v = cmulf(z[3], w1); u = z[1];
        z[1] = make_float2(u.x + v.x, u.y + v.y);
        z[3] = make_float2(u.x - v.x, u.y - v.y);
    }
}

// FFT of weight rows, store conjugated (correlation kernel).
__global__ __launch_bounds__(256) void fft_w_kernel() {
    int t = threadIdx.x & 31, w = threadIdx.x >> 5;
    int row = blockIdx.x * 8 + w;                 // c*51+dy, < 6528
    const float* src = g_wpad + row * WROW;
    float2 z[4];
    z[0] = make_float2(src[t], 0.f);
    z[1] = make_float2((t + 32) < KSZ ? src[t + 32] : 0.f, 0.f);
    z[2] = make_float2(0.f, 0.f);
    z[3] = make_float2(0.f, 0.f);
    fft128_fwd(z, t);
    float2* dst = g_wf + (size_t)row * NBIN;
    dst[t]      = make_float2(z[0].x, -z[0].y);
    dst[t + 32] = make_float2(z[1].x, -z[1].y);
    dst[t + 64] = make_float2(z[2].x, -z[2].y);
    dst[t + 96] = make_float2(z[3].x, -z[3].y);
}

// FFT of batch-pair-packed input rows.
__global__ __launch_bounds__(256) void fft_x_kernel(const float* __restrict__ x) {
    int t = threadIdx.x & 31, w = threadIdx.x >> 5;
    int row = blockIdx.x * 8 + w;                 // pimg*64 + y, < 65536
    int pimg = row >> 6;
    int y    = row & 63;
    int pb   = pimg >> 7;
    int c    = pimg & 127;
    const float* r0 = x + (((size_t)(2 * pb)     * NCH + c) * 64 + y) * 64;
    const float* r1 = x + (((size_t)(2 * pb + 1) * NCH + c) * 64 + y) * 64;
    float2 z[4];
    z[0] = make_float2(r0[t],      r1[t]);
    z[1] = make_float2(r0[t + 32], r1[t + 32]);
    z[2] = make_float2(0.f, 0.f);
    z[3] = make_float2(0.f, 0.f);
    fft128_fwd(z, t);
    float2* dst = g_xf + (size_t)row * NBIN;
    dst[t]      = z[0];
    dst[t + 32] = z[1];
    dst[t + 64] = z[2];
    dst[t + 96] = z[3];
}

// 51-tap conv along y per frequency slot. CTA = (packed image, 64-bin half).
__global__ __launch_bounds__(256, 2) void yconv_kernel() {
    extern __shared__ float2 sm2[];
    float2* Xs = sm2;                 // XPAD * 64
    float2* Ws = sm2 + XPAD * 64;     // KSZ * 64
    const int pimg = blockIdx.x >> 1;
    const int binb = (blockIdx.x & 1) * 64;
    const int c    = pimg & (NCH - 1);
    const int tid  = threadIdx.x;

    for (int i = tid; i < KSZ * 64; i += 256) {
        int dy = i >> 6, f = i & 63;
        Ws[i] = g_wf[((size_t)c * KSZ + dy) * NBIN + binb + f];
    }
    const float2* xsrc = g_xf + (size_t)pimg * (YDIM * NBIN) + binb;
    for (int i = tid; i < XPAD * 64; i += 256) {
        int s = i >> 6, f = i & 63;
        int ys = s - RAD;
        float2 v = make_float2(0.f, 0.f);
        if ((unsigned)ys < (unsigned)YDIM) v = xsrc[(size_t)ys * NBIN + f];
        Xs[i] = v;
    }
    __syncthreads();

    float2* dst = g_sf + (size_t)pimg * (YDIM * NBIN) + binb;
    for (int task = tid; task < 512; task += 256) {
        int yb = task >> 6, f = task & 63;
        int y0 = yb * 8;
        const float2* base = Xs + y0 * 64 + f;
        const float2* wp   = Ws + f;

        float2 acc[8], win[8];
#pragma unroll
        for (int i = 0; i < 8; ++i) acc[i] = make_float2(0.f, 0.f);
#pragma unroll
        for (int j = 0; j < 7; ++j) win[j] = base[j * 64];

#pragma unroll
        for (int dy = 0; dy < KSZ; ++dy) {
            win[(dy + 7) & 7] = base[(dy + 7) * 64];
            float2 wv = wp[dy * 64];
#pragma unroll
            for (int i = 0; i < 8; ++i) {
                float2 xv = win[(dy + i) & 7];
                acc[i].x = fmaf(xv.x, wv.x, fmaf(-xv.y, wv.y, acc[i].x));
                acc[i].y = fmaf(xv.x, wv.y, fmaf( xv.y, wv.x, acc[i].y));
            }
        }
#pragma unroll
        for (int i = 0; i < 8; ++i)
            dst[(size_t)(y0 + i) * NBIN + f] = acc[i];
    }
}

// Inverse FFT, crop, unpack batch pair.
__global__ __launch_bounds__(256) void ifft_kernel(float* __restrict__ out) {
    int t = threadIdx.x & 31, w = threadIdx.x >> 5;
    int row = blockIdx.x * 8 + w;                 // < 65536
    const float2* S = g_sf + (size_t)row * NBIN;
    float2 z[4];
    z[0] = S[t];
    z[1] = S[t + 32];
    z[2] = S[t + 64];
    z[3] = S[t + 96];
    fft128_inv(z, t);

    int pimg = row >> 6, y = row & 63;
    int pb = pimg >> 7, c = pimg & 127;
    float* o0 = out + (((size_t)(2 * pb)     * NCH + c) * 64 + y) * 64;
    float* o1 = out + (((size_t)(2 * pb + 1) * NCH + c) * 64 + y) * 64;
    const float s = 1.0f / 128.0f;
    // natural sample n at z[j], n = t + 32j; output x = (n + 25) mod 128 if < 64
    o0[t + 25] = z[0].x * s;
    o1[t + 25] = z[0].y * s;
    if (t < 7) {
        o0[t + 57] = z[1].x * s;
        o1[t + 57] = z[1].y * s;
    } else {
        o0[t - 7] = z[3].x * s;
        o1[t - 7] = z[3].y * s;
    }
}

extern "C" void kernel_launch(void* const* d_in, const int* in_sizes, int n_in,
                              void* d_out, int out_size) {
    const float* x   = (const float*)d_in[0];   // 16*128*64*64
    const float* wc  = (const float*)d_in[1];   // 128*169
    const float* kpe = (const float*)d_in[2];   // 51*51
    float* out = (float*)d_out;

    const int total_w = NCH * KSZ * WROW;
    build_weights_kernel<<<(total_w + 255) / 256, 256>>>(wc, kpe);

    fft_w_kernel<<<(NCH * KSZ) / 8, 256>>>();        // 6528 rows
    fft_x_kernel<<<NPROWS / 8, 256>>>(x);            // 65536 packed rows

    const size_t ysmem = (size_t)(XPAD + KSZ) * 64 * sizeof(float2);  // 84480 B
    cudaFuncSetAttribute(yconv_kernel,
                         cudaFuncAttributeMaxDynamicSharedMemorySize, (int)ysmem);
    yconv_kernel<<<NPIMG * 2, 256, ysmem>>>();

    ifft_kernel<<<NPROWS / 8, 256>>>(out);
}